// round 1
// baseline (speedup 1.0000x reference)
#include <cuda_runtime.h>
#include <stdint.h>

#define N_NODES 100000
#define N_EDGES 1600000
#define N_GRAPHS 256

// ---------------- scratch (no allocation allowed -> device globals) ----------
__device__ float g_norm_src[N_NODES];           // deg_out -> rsqrt norm
__device__ float g_norm_dst[N_NODES];           // deg_in  -> rsqrt norm
__device__ float g_h[(size_t)N_NODES * 128];    // current features
__device__ float g_m[(size_t)N_NODES * 128];    // aggregation buffer
__device__ int   g_flag_idx;                    // 1 = src/dst are int32, 0 = int64
__device__ int   g_flag_gid;                    // 1 = graph_id is int32, 0 = int64

// ---------------- helpers ----------------------------------------------------
__device__ __forceinline__ int load_idx(const void* p, long long i, int is32) {
    if (is32) return ((const int*)p)[i];
    return (int)(((const long long*)p)[i]);
}

__global__ void reset_flags_kernel() { g_flag_idx = 0; g_flag_gid = 0; }

// If buffer holds int64 values < 2^31, every odd 32-bit word is 0.
// If it holds int32 data, odd words are real (mostly nonzero) values.
__global__ void detect_idx_kernel(const unsigned* w, long long nw) {
    long long i = (long long)blockIdx.x * blockDim.x + threadIdx.x;
    long long stride = (long long)gridDim.x * blockDim.x;
    for (; i < nw; i += stride)
        if ((i & 1) && w[i]) g_flag_idx = 1;   // benign race, same value
}
__global__ void detect_gid_kernel(const unsigned* w, long long nw) {
    long long i = (long long)blockIdx.x * blockDim.x + threadIdx.x;
    long long stride = (long long)gridDim.x * blockDim.x;
    for (; i < nw; i += stride)
        if ((i & 1) && w[i]) g_flag_gid = 1;
}

__global__ void zero_kernel(float* p, long long n) {
    long long i = (long long)blockIdx.x * blockDim.x + threadIdx.x;
    long long stride = (long long)gridDim.x * blockDim.x;
    for (; i < n; i += stride) p[i] = 0.0f;
}

// ---------------- degrees / norms --------------------------------------------
__global__ void deg_kernel(const void* src, const void* dst) {
    int is32 = g_flag_idx;
    long long i = (long long)blockIdx.x * blockDim.x + threadIdx.x;
    long long stride = (long long)gridDim.x * blockDim.x;
    for (; i < N_EDGES; i += stride) {
        atomicAdd(&g_norm_src[load_idx(src, i, is32)], 1.0f);
        atomicAdd(&g_norm_dst[load_idx(dst, i, is32)], 1.0f);
    }
}

__global__ void norm_kernel() {
    long long i = (long long)blockIdx.x * blockDim.x + threadIdx.x;
    if (i >= N_NODES) return;
    float a = g_norm_src[i];
    float b = g_norm_dst[i];
    g_norm_src[i] = (a > 0.0f) ? rsqrtf(a) : 0.0f;
    g_norm_dst[i] = (b > 0.0f) ? rsqrtf(b) : 0.0f;
}

// ---------------- edge scatter: m[dst] += x[src] * norm_src[src] -------------
template <int D>
__global__ void scatter_kernel(const float* __restrict__ x,
                               const void* __restrict__ src,
                               const void* __restrict__ dst,
                               float* __restrict__ m) {
    int is32 = g_flag_idx;
    long long idx = (long long)blockIdx.x * blockDim.x + threadIdx.x;
    long long e = idx >> 5;          // one warp per edge
    int lane = (int)(idx & 31);
    if (e >= N_EDGES) return;
    int s = load_idx(src, e, is32);
    int t = load_idx(dst, e, is32);
    float ns = g_norm_src[s];
    const float* xi = x + (long long)s * D;
    float* mo = m + (long long)t * D;
#pragma unroll
    for (int f = lane; f < D; f += 32)
        atomicAdd(&mo[f], xi[f] * ns);
}

// ------- fused: (m * norm_dst) @ W + b, relu, optional sum-pool --------------
template <int DIN, int DOUT, int NPB, bool POOL>
__global__ void gemm_relu_kernel(const float* __restrict__ m,
                                 const float* __restrict__ W,
                                 const float* __restrict__ b,
                                 float* __restrict__ out,
                                 const void* __restrict__ gid) {
    __shared__ float sm[NPB][DIN];
    int tx = threadIdx.x;            // output feature
    int ty = threadIdx.y;            // node within block
    long long n = (long long)blockIdx.x * NPB + ty;
    bool valid = (n < N_NODES);
    long long nc = valid ? n : (N_NODES - 1);
    float nd = g_norm_dst[nc];
    for (int k = tx; k < DIN; k += DOUT)
        sm[ty][k] = m[nc * DIN + k] * nd;
    __syncthreads();

    float acc = b[tx];
#pragma unroll 8
    for (int k = 0; k < DIN; k++)
        acc = fmaf(sm[ty][k], W[k * DOUT + tx], acc);
    acc = fmaxf(acc, 0.0f);

    if (valid) {
        if (POOL) {
            int g = load_idx(gid, nc, g_flag_gid);
            atomicAdd(&out[(long long)g * DOUT + tx], acc);
        } else {
            out[nc * DOUT + tx] = acc;
        }
    }
}

// ---------------- launch ------------------------------------------------------
extern "C" void kernel_launch(void* const* d_in, const int* in_sizes, int n_in,
                              void* d_out, int out_size) {
    const float* h        = (const float*)d_in[0];
    const void*  src      = d_in[1];
    const void*  dst      = d_in[2];
    const void*  graph_id = d_in[3];
    const float* W1 = (const float*)d_in[4];
    const float* b1 = (const float*)d_in[5];
    const float* W2 = (const float*)d_in[6];
    const float* b2 = (const float*)d_in[7];
    const float* W3 = (const float*)d_in[8];
    const float* b3 = (const float*)d_in[9];
    float* out = (float*)d_out;

    float *p_ns, *p_nd, *p_h, *p_m;
    cudaGetSymbolAddress((void**)&p_ns, g_norm_src);
    cudaGetSymbolAddress((void**)&p_nd, g_norm_dst);
    cudaGetSymbolAddress((void**)&p_h,  g_h);
    cudaGetSymbolAddress((void**)&p_m,  g_m);

    // 0) dtype detection
    reset_flags_kernel<<<1, 1>>>();
    detect_idx_kernel<<<512, 256>>>((const unsigned*)src, (long long)N_EDGES);
    detect_gid_kernel<<<128, 256>>>((const unsigned*)graph_id, (long long)N_NODES);

    // 1) degrees -> norms
    zero_kernel<<<(N_NODES + 255) / 256, 256>>>(p_ns, N_NODES);
    zero_kernel<<<(N_NODES + 255) / 256, 256>>>(p_nd, N_NODES);
    deg_kernel<<<2048, 256>>>(src, dst);
    norm_kernel<<<(N_NODES + 255) / 256, 256>>>();

    const long long scatter_threads = (long long)N_EDGES * 32;
    const int scatter_blocks = (int)((scatter_threads + 255) / 256);

    // 2) layer 1: 64 -> 128
    zero_kernel<<<8192, 256>>>(p_m, (long long)N_NODES * 64);
    scatter_kernel<64><<<scatter_blocks, 256>>>(h, src, dst, p_m);
    {
        dim3 blk(128, 2);
        int grid = (N_NODES + 1) / 2;
        gemm_relu_kernel<64, 128, 2, false><<<grid, blk>>>(p_m, W1, b1, p_h, nullptr);
    }

    // 3) layer 2: 128 -> 128
    zero_kernel<<<8192, 256>>>(p_m, (long long)N_NODES * 128);
    scatter_kernel<128><<<scatter_blocks, 256>>>(p_h, src, dst, p_m);
    {
        dim3 blk(128, 2);
        int grid = (N_NODES + 1) / 2;
        gemm_relu_kernel<128, 128, 2, false><<<grid, blk>>>(p_m, W2, b2, p_h, nullptr);
    }

    // 4) layer 3: 128 -> 64, fused sum-pool into d_out
    zero_kernel<<<8192, 256>>>(p_m, (long long)N_NODES * 128);
    scatter_kernel<128><<<scatter_blocks, 256>>>(p_h, src, dst, p_m);
    zero_kernel<<<(N_GRAPHS * 64 + 255) / 256, 256>>>(out, (long long)N_GRAPHS * 64);
    {
        dim3 blk(64, 4);
        int grid = (N_NODES + 3) / 4;
        gemm_relu_kernel<128, 64, 4, true><<<grid, blk>>>(p_m, W3, b3, out, graph_id);
    }
}

// round 3
// speedup vs baseline: 1.4584x; 1.4584x over previous
#include <cuda_runtime.h>
#include <stdint.h>

#define N_NODES 100000
#define N_EDGES 1600000
#define N_GRAPHS 256

// ---------------- scratch (no allocation allowed -> device globals) ----------
__device__ int   g_deg_out[N_NODES];
__device__ int   g_deg_in[N_NODES];
__device__ float g_norm_src[N_NODES];
__device__ float g_norm_dst[N_NODES];
__device__ int   g_row[N_NODES + 1];            // CSR row offsets (by dst)
__device__ int   g_cur[N_NODES];                // fill cursors
__device__ int   g_csr[N_EDGES];                // src index per CSR slot
__device__ float g_bufA[(size_t)N_NODES * 128];
__device__ float g_bufB[(size_t)N_NODES * 128];
__device__ int   g_flag_idx;                    // 1 = src/dst are int32
__device__ int   g_flag_gid;                    // 1 = graph_id is int32

// ---------------- helpers ----------------------------------------------------
__device__ __forceinline__ int load_idx(const void* p, long long i, int is32) {
    if (is32) return ((const int*)p)[i];
    return (int)(((const long long*)p)[i]);
}

__global__ void reset_flags_kernel() { g_flag_idx = 0; g_flag_gid = 0; }

// int64 values < 2^31 -> every odd 32-bit word is 0; int32 data -> nonzero.
__global__ void detect_idx_kernel(const unsigned* w, long long nw) {
    long long i = (long long)blockIdx.x * blockDim.x + threadIdx.x;
    long long stride = (long long)gridDim.x * blockDim.x;
    for (; i < nw; i += stride)
        if ((i & 1) && w[i]) g_flag_idx = 1;
}
__global__ void detect_gid_kernel(const unsigned* w, long long nw) {
    long long i = (long long)blockIdx.x * blockDim.x + threadIdx.x;
    long long stride = (long long)gridDim.x * blockDim.x;
    for (; i < nw; i += stride)
        if ((i & 1) && w[i]) g_flag_gid = 1;
}

__global__ void zero_int2_kernel() {
    int i = blockIdx.x * blockDim.x + threadIdx.x;
    if (i < N_NODES) { g_deg_out[i] = 0; g_deg_in[i] = 0; }
}
__global__ void zero_out_kernel(float* p, int n) {
    int i = blockIdx.x * blockDim.x + threadIdx.x;
    if (i < n) p[i] = 0.0f;
}

// ---------------- degrees ----------------------------------------------------
__global__ void deg_kernel(const void* src, const void* dst) {
    int is32 = g_flag_idx;
    long long i = (long long)blockIdx.x * blockDim.x + threadIdx.x;
    long long stride = (long long)gridDim.x * blockDim.x;
    for (; i < N_EDGES; i += stride) {
        atomicAdd(&g_deg_out[load_idx(src, i, is32)], 1);
        atomicAdd(&g_deg_in[load_idx(dst, i, is32)], 1);
    }
}

__global__ void norm_kernel() {
    int i = blockIdx.x * blockDim.x + threadIdx.x;
    if (i >= N_NODES) return;
    int a = g_deg_out[i];
    int b = g_deg_in[i];
    g_norm_src[i] = (a > 0) ? rsqrtf((float)a) : 0.0f;
    g_norm_dst[i] = (b > 0) ? rsqrtf((float)b) : 0.0f;
}

// single-block exclusive scan of deg_in -> row offsets + cursors
__global__ void scan_kernel() {
    __shared__ int ssum[1024];
    const int CH = (N_NODES + 1023) / 1024;   // 98
    int t = threadIdx.x;
    int lo = t * CH;
    int hi = min(lo + CH, N_NODES);
    int s = 0;
    for (int i = lo; i < hi; i++) s += g_deg_in[i];
    ssum[t] = s;
    __syncthreads();
    for (int off = 1; off < 1024; off <<= 1) {
        int v = (t >= off) ? ssum[t - off] : 0;
        __syncthreads();
        ssum[t] += v;
        __syncthreads();
    }
    int run = (t > 0) ? ssum[t - 1] : 0;
    for (int i = lo; i < hi; i++) {
        g_row[i] = run;
        g_cur[i] = run;
        run += g_deg_in[i];
    }
    if (t == 1023) g_row[N_NODES] = ssum[1023];
}

__global__ void fill_csr_kernel(const void* src, const void* dst) {
    int is32 = g_flag_idx;
    long long i = (long long)blockIdx.x * blockDim.x + threadIdx.x;
    long long stride = (long long)gridDim.x * blockDim.x;
    for (; i < N_EDGES; i += stride) {
        int d = load_idx(dst, i, is32);
        int pos = atomicAdd(&g_cur[d], 1);
        g_csr[pos] = load_idx(src, i, is32);
    }
}

// ---------------- prescale: bufA = h * norm_src (64-dim) ---------------------
__global__ void prescale_kernel(const float* __restrict__ h) {
    int i = blockIdx.x * blockDim.x + threadIdx.x;   // over N_NODES*64
    if (i >= N_NODES * 64) return;
    int n = i >> 6;
    g_bufA[i] = h[i] * g_norm_src[n];
}

// ------- CSR gather: out[n] = (sum_{e in in(n)} x[src_e]) * norm_dst[n] ------
template <int D>
__global__ void gather_kernel(const float* __restrict__ x,
                              float* __restrict__ out) {
    constexpr int VEC = D / 32;                      // floats per lane
    int warp = (blockIdx.x << 3) | (threadIdx.x >> 5);
    int lane = threadIdx.x & 31;
    if (warp >= N_NODES) return;
    int lo = g_row[warp], hi = g_row[warp + 1];
    float acc[VEC];
#pragma unroll
    for (int v = 0; v < VEC; v++) acc[v] = 0.0f;
    for (int j = lo; j < hi; j++) {
        int s = g_csr[j];
        if (VEC == 2) {
            float2 val = ((const float2*)(x + (size_t)s * D))[lane];
            acc[0] += val.x; acc[1] += val.y;
        } else {
            float4 val = ((const float4*)(x + (size_t)s * D))[lane];
            acc[0] += val.x; acc[1] += val.y; acc[2] += val.z; acc[3] += val.w;
        }
    }
    float nd = g_norm_dst[warp];
    if (VEC == 2) {
        float2 r; r.x = acc[0] * nd; r.y = acc[1] * nd;
        ((float2*)(out + (size_t)warp * D))[lane] = r;
    } else {
        float4 r; r.x = acc[0] * nd; r.y = acc[1] * nd; r.z = acc[2] * nd; r.w = acc[3] * nd;
        ((float4*)(out + (size_t)warp * D))[lane] = r;
    }
}

// final layer gather: epilogue = relu(acc*nd + b3) then pooled atomicAdd
__global__ void gather_pool_kernel(const float* __restrict__ x,
                                   const float* __restrict__ b3,
                                   const void* __restrict__ gid,
                                   float* __restrict__ out) {
    int warp = (blockIdx.x << 3) | (threadIdx.x >> 5);
    int lane = threadIdx.x & 31;
    if (warp >= N_NODES) return;
    int lo = g_row[warp], hi = g_row[warp + 1];
    float a0 = 0.0f, a1 = 0.0f;
    for (int j = lo; j < hi; j++) {
        int s = g_csr[j];
        float2 val = ((const float2*)(x + (size_t)s * 64))[lane];
        a0 += val.x; a1 += val.y;
    }
    float nd = g_norm_dst[warp];
    float2 b = ((const float2*)b3)[lane];
    a0 = fmaxf(fmaf(a0, nd, b.x), 0.0f);
    a1 = fmaxf(fmaf(a1, nd, b.y), 0.0f);
    int g = load_idx(gid, warp, g_flag_gid);
    atomicAdd(&out[(size_t)g * 64 + lane * 2],     a0);
    atomicAdd(&out[(size_t)g * 64 + lane * 2 + 1], a1);
}

// ------- GEMM: out = epilogue(m @ W + b); 4 node-rows per thread -------------
// EPI==1: out = relu(acc + b) * norm_src[n]   (mid layers)
// EPI==0: out = acc                            (layer-3 transform-first)
template <int DIN, int DOUT, int EPI>
__global__ void gemm_kernel(const float* __restrict__ m,
                            const float* __restrict__ W,
                            const float* __restrict__ b,
                            float* __restrict__ out) {
    constexpr int TY  = 256 / DOUT;   // thread rows
    constexpr int R   = 4;            // nodes per thread
    constexpr int NPB = TY * R;       // nodes per block
    __shared__ float sm[NPB * DIN];
    int tx = threadIdx.x;
    int ty = threadIdx.y;
    int tid = ty * DOUT + tx;
    size_t base = (size_t)blockIdx.x * NPB;

    // cooperative, fully-contiguous load of NPB node rows
    const float* src = m + base * DIN;
    for (int i = tid; i < NPB * DIN; i += 256) sm[i] = src[i];
    __syncthreads();

    float acc[R];
    float bias = EPI ? b[tx] : 0.0f;
#pragma unroll
    for (int r = 0; r < R; r++) acc[r] = bias;

#pragma unroll 4
    for (int k = 0; k < DIN; k++) {
        float w = W[k * DOUT + tx];
#pragma unroll
        for (int r = 0; r < R; r++)
            acc[r] = fmaf(sm[(ty * R + r) * DIN + k], w, acc[r]);
    }

#pragma unroll
    for (int r = 0; r < R; r++) {
        size_t n = base + ty * R + r;
        float v = acc[r];
        if (EPI) v = fmaxf(v, 0.0f) * g_norm_src[n];
        out[n * DOUT + tx] = v;
    }
}

// ---------------- launch ------------------------------------------------------
extern "C" void kernel_launch(void* const* d_in, const int* in_sizes, int n_in,
                              void* d_out, int out_size) {
    const float* h        = (const float*)d_in[0];
    const void*  src      = d_in[1];
    const void*  dst      = d_in[2];
    const void*  graph_id = d_in[3];
    const float* W1 = (const float*)d_in[4];
    const float* b1 = (const float*)d_in[5];
    const float* W2 = (const float*)d_in[6];
    const float* b2 = (const float*)d_in[7];
    const float* W3 = (const float*)d_in[8];
    const float* b3 = (const float*)d_in[9];
    float* out = (float*)d_out;

    float *pA, *pB;
    cudaGetSymbolAddress((void**)&pA, g_bufA);
    cudaGetSymbolAddress((void**)&pB, g_bufB);

    // 0) dtype detection
    reset_flags_kernel<<<1, 1>>>();
    detect_idx_kernel<<<512, 256>>>((const unsigned*)src, (long long)N_EDGES);
    detect_gid_kernel<<<128, 256>>>((const unsigned*)graph_id, (long long)N_NODES);

    // 1) degrees -> norms, CSR build
    zero_int2_kernel<<<(N_NODES + 255) / 256, 256>>>();
    deg_kernel<<<2048, 256>>>(src, dst);
    norm_kernel<<<(N_NODES + 255) / 256, 256>>>();
    scan_kernel<<<1, 1024>>>();
    fill_csr_kernel<<<2048, 256>>>(src, dst);

    const int GATHER_GRID = (N_NODES + 7) / 8;     // 8 warps/block

    // 2) layer 1: prescale -> gather(64) -> gemm 64->128 (+relu,*norm_src)
    prescale_kernel<<<(N_NODES * 64 + 255) / 256, 256>>>(h);
    gather_kernel<64><<<GATHER_GRID, 256>>>(pA, pB);
    {
        dim3 blk(128, 2);
        gemm_kernel<64, 128, 1><<<N_NODES / 8, blk>>>(pB, W1, b1, pA);
    }

    // 3) layer 2: gather(128) -> gemm 128->128 (+relu,*norm_src)
    gather_kernel<128><<<GATHER_GRID, 256>>>(pA, pB);
    {
        dim3 blk(128, 2);
        gemm_kernel<128, 128, 1><<<N_NODES / 8, blk>>>(pB, W2, b2, pA);
    }

    // 4) layer 3: transform first (gemm 128->64, no epi), then gather+pool
    {
        dim3 blk(64, 4);
        gemm_kernel<128, 64, 0><<<N_NODES / 16, blk>>>(pA, W3, nullptr, pB);
    }
    zero_out_kernel<<<(N_GRAPHS * 64 + 255) / 256, 256>>>(out, N_GRAPHS * 64);
    gather_pool_kernel<<<GATHER_GRID, 256>>>(pB, b3, graph_id, out);
}

// round 4
// speedup vs baseline: 1.7539x; 1.2026x over previous
#include <cuda_runtime.h>
#include <stdint.h>

#define N_NODES 100000
#define N_EDGES 1600000
#define N_GRAPHS 256

// ---------------- scratch (no allocation allowed -> device globals) ----------
__device__ int   g_deg_out[N_NODES];
__device__ int   g_deg_in[N_NODES];
__device__ float g_norm_src[N_NODES];
__device__ float g_norm_dst[N_NODES];
__device__ int   g_row[N_NODES + 1];            // CSR row offsets (by dst)
__device__ int   g_cur[N_NODES];                // fill cursors
__device__ int   g_csr[N_EDGES];                // src index per CSR slot
__device__ float g_bufA[(size_t)N_NODES * 128];
__device__ float g_bufB[(size_t)N_NODES * 128];
__device__ int   g_flag_idx;                    // 1 = src/dst are int32
__device__ int   g_flag_gid;                    // 1 = graph_id is int32

// ---------------- helpers ----------------------------------------------------
__device__ __forceinline__ int load_idx(const void* p, long long i, int is32) {
    if (is32) return ((const int*)p)[i];
    return (int)(((const long long*)p)[i]);
}

// init: reset flags + zero degree arrays (one launch)
__global__ void init_kernel() {
    int i = blockIdx.x * blockDim.x + threadIdx.x;
    if (i == 0) { g_flag_idx = 0; g_flag_gid = 0; }
    if (i < N_NODES) { g_deg_out[i] = 0; g_deg_in[i] = 0; }
}

// int64 values < 2^31 -> every odd 32-bit word is 0; int32 data -> nonzero.
__global__ void detect_all_kernel(const unsigned* s, const unsigned* g) {
    long long i = (long long)blockIdx.x * blockDim.x + threadIdx.x;
    long long stride = (long long)gridDim.x * blockDim.x;
    for (long long j = i; j < N_EDGES; j += stride)
        if ((j & 1) && s[j]) g_flag_idx = 1;
    for (long long j = i; j < N_NODES; j += stride)
        if ((j & 1) && g[j]) g_flag_gid = 1;
}

__global__ void zero_out_kernel(float* p, int n) {
    int i = blockIdx.x * blockDim.x + threadIdx.x;
    if (i < n) p[i] = 0.0f;
}

// ---------------- degrees ----------------------------------------------------
__global__ void deg_kernel(const void* src, const void* dst) {
    int is32 = g_flag_idx;
    long long i = (long long)blockIdx.x * blockDim.x + threadIdx.x;
    long long stride = (long long)gridDim.x * blockDim.x;
    for (; i < N_EDGES; i += stride) {
        atomicAdd(&g_deg_out[load_idx(src, i, is32)], 1);
        atomicAdd(&g_deg_in[load_idx(dst, i, is32)], 1);
    }
}

__global__ void norm_kernel() {
    int i = blockIdx.x * blockDim.x + threadIdx.x;
    if (i >= N_NODES) return;
    int a = g_deg_out[i];
    int b = g_deg_in[i];
    g_norm_src[i] = (a > 0) ? rsqrtf((float)a) : 0.0f;
    g_norm_dst[i] = (b > 0) ? rsqrtf((float)b) : 0.0f;
}

// single-block exclusive scan of deg_in -> row offsets + cursors
__global__ void scan_kernel() {
    __shared__ int ssum[1024];
    const int CH = (N_NODES + 1023) / 1024;   // 98
    int t = threadIdx.x;
    int lo = t * CH;
    int hi = min(lo + CH, N_NODES);
    int s = 0;
    for (int i = lo; i < hi; i++) s += g_deg_in[i];
    ssum[t] = s;
    __syncthreads();
    for (int off = 1; off < 1024; off <<= 1) {
        int v = (t >= off) ? ssum[t - off] : 0;
        __syncthreads();
        ssum[t] += v;
        __syncthreads();
    }
    int run = (t > 0) ? ssum[t - 1] : 0;
    for (int i = lo; i < hi; i++) {
        g_row[i] = run;
        g_cur[i] = run;
        run += g_deg_in[i];
    }
    if (t == 1023) g_row[N_NODES] = ssum[1023];
}

__global__ void fill_csr_kernel(const void* src, const void* dst) {
    int is32 = g_flag_idx;
    long long i = (long long)blockIdx.x * blockDim.x + threadIdx.x;
    long long stride = (long long)gridDim.x * blockDim.x;
    for (; i < N_EDGES; i += stride) {
        int d = load_idx(dst, i, is32);
        int pos = atomicAdd(&g_cur[d], 1);
        g_csr[pos] = load_idx(src, i, is32);
    }
}

// ---------------- prescale: bufA = h * norm_src (64-dim) ---------------------
__global__ void prescale_kernel(const float* __restrict__ h) {
    int i = blockIdx.x * blockDim.x + threadIdx.x;   // over N_NODES*64
    if (i >= N_NODES * 64) return;
    int n = i >> 6;
    g_bufA[i] = h[i] * g_norm_src[n];
}

// ------- CSR gather: out[n] = (sum_{e in in(n)} x[src_e]) * norm_dst[n] ------
// 2-edge software pipelining for MLP.
template <int D>
__global__ void gather_kernel(const float* __restrict__ x,
                              float* __restrict__ out) {
    int warp = (blockIdx.x << 3) | (threadIdx.x >> 5);
    int lane = threadIdx.x & 31;
    if (warp >= N_NODES) return;
    int lo = g_row[warp], hi = g_row[warp + 1];
    if (D == 64) {
        float a0 = 0.f, a1 = 0.f, b0 = 0.f, b1 = 0.f;
        int j = lo;
        for (; j + 1 < hi; j += 2) {
            int s0 = g_csr[j], s1 = g_csr[j + 1];
            float2 v0 = ((const float2*)(x + (size_t)s0 * 64))[lane];
            float2 v1 = ((const float2*)(x + (size_t)s1 * 64))[lane];
            a0 += v0.x; a1 += v0.y;
            b0 += v1.x; b1 += v1.y;
        }
        if (j < hi) {
            int s0 = g_csr[j];
            float2 v0 = ((const float2*)(x + (size_t)s0 * 64))[lane];
            a0 += v0.x; a1 += v0.y;
        }
        float nd = g_norm_dst[warp];
        float2 r; r.x = (a0 + b0) * nd; r.y = (a1 + b1) * nd;
        ((float2*)(out + (size_t)warp * 64))[lane] = r;
    } else {
        float a0=0.f,a1=0.f,a2=0.f,a3=0.f,b0=0.f,b1=0.f,b2=0.f,b3=0.f;
        int j = lo;
        for (; j + 1 < hi; j += 2) {
            int s0 = g_csr[j], s1 = g_csr[j + 1];
            float4 v0 = ((const float4*)(x + (size_t)s0 * 128))[lane];
            float4 v1 = ((const float4*)(x + (size_t)s1 * 128))[lane];
            a0 += v0.x; a1 += v0.y; a2 += v0.z; a3 += v0.w;
            b0 += v1.x; b1 += v1.y; b2 += v1.z; b3 += v1.w;
        }
        if (j < hi) {
            int s0 = g_csr[j];
            float4 v0 = ((const float4*)(x + (size_t)s0 * 128))[lane];
            a0 += v0.x; a1 += v0.y; a2 += v0.z; a3 += v0.w;
        }
        float nd = g_norm_dst[warp];
        float4 r;
        r.x = (a0 + b0) * nd; r.y = (a1 + b1) * nd;
        r.z = (a2 + b2) * nd; r.w = (a3 + b3) * nd;
        ((float4*)(out + (size_t)warp * 128))[lane] = r;
    }
}

// final layer gather: epilogue = relu(acc*nd + b3) then pooled atomicAdd
__global__ void gather_pool_kernel(const float* __restrict__ x,
                                   const float* __restrict__ b3,
                                   const void* __restrict__ gid,
                                   float* __restrict__ out) {
    int warp = (blockIdx.x << 3) | (threadIdx.x >> 5);
    int lane = threadIdx.x & 31;
    if (warp >= N_NODES) return;
    int lo = g_row[warp], hi = g_row[warp + 1];
    float a0 = 0.f, a1 = 0.f, b0 = 0.f, b1 = 0.f;
    int j = lo;
    for (; j + 1 < hi; j += 2) {
        int s0 = g_csr[j], s1 = g_csr[j + 1];
        float2 v0 = ((const float2*)(x + (size_t)s0 * 64))[lane];
        float2 v1 = ((const float2*)(x + (size_t)s1 * 64))[lane];
        a0 += v0.x; a1 += v0.y;
        b0 += v1.x; b1 += v1.y;
    }
    if (j < hi) {
        int s0 = g_csr[j];
        float2 v0 = ((const float2*)(x + (size_t)s0 * 64))[lane];
        a0 += v0.x; a1 += v0.y;
    }
    float nd = g_norm_dst[warp];
    float2 bb = ((const float2*)b3)[lane];
    float r0 = fmaxf(fmaf(a0 + b0, nd, bb.x), 0.0f);
    float r1 = fmaxf(fmaf(a1 + b1, nd, bb.y), 0.0f);
    int g = load_idx(gid, warp, g_flag_gid);
    atomicAdd(&out[(size_t)g * 64 + lane * 2],     r0);
    atomicAdd(&out[(size_t)g * 64 + lane * 2 + 1], r1);
}

// ------- GEMM: out = epilogue(m @ W + b); R node-rows per thread, k by 4 -----
// EPI==1: out = relu(acc + b) * norm_src[n]   (mid layers)
// EPI==0: out = acc                            (layer-3 transform-first)
template <int DIN, int DOUT, int R, int EPI>
__global__ void gemm_kernel(const float4* __restrict__ m4,
                            const float* __restrict__ W,
                            const float* __restrict__ b,
                            float* __restrict__ out) {
    constexpr int TY  = 256 / DOUT;
    constexpr int NPB = TY * R;
    constexpr int K4  = DIN / 4;
    __shared__ float4 sm[NPB * K4];
    int tx = threadIdx.x;            // output feature
    int ty = threadIdx.y;
    int tid = ty * DOUT + tx;
    size_t base = (size_t)blockIdx.x * NPB;

    // cooperative contiguous float4 load of NPB node rows
    const float4* src = m4 + base * K4;
#pragma unroll
    for (int i = tid; i < NPB * K4; i += 256) sm[i] = src[i];
    __syncthreads();

    float bias = EPI ? b[tx] : 0.0f;
    float acc[R];
#pragma unroll
    for (int r = 0; r < R; r++) acc[r] = bias;

#pragma unroll 4
    for (int k4 = 0; k4 < K4; k4++) {
        int k = k4 * 4;
        float w0 = W[(k + 0) * DOUT + tx];
        float w1 = W[(k + 1) * DOUT + tx];
        float w2 = W[(k + 2) * DOUT + tx];
        float w3 = W[(k + 3) * DOUT + tx];
#pragma unroll
        for (int r = 0; r < R; r++) {
            float4 v = sm[(ty * R + r) * K4 + k4];
            acc[r] = fmaf(v.x, w0, acc[r]);
            acc[r] = fmaf(v.y, w1, acc[r]);
            acc[r] = fmaf(v.z, w2, acc[r]);
            acc[r] = fmaf(v.w, w3, acc[r]);
        }
    }

#pragma unroll
    for (int r = 0; r < R; r++) {
        size_t n = base + ty * R + r;
        float v = acc[r];
        if (EPI) v = fmaxf(v, 0.0f) * g_norm_src[n];
        out[n * DOUT + tx] = v;
    }
}

// ---------------- launch ------------------------------------------------------
extern "C" void kernel_launch(void* const* d_in, const int* in_sizes, int n_in,
                              void* d_out, int out_size) {
    const float* h        = (const float*)d_in[0];
    const void*  src      = d_in[1];
    const void*  dst      = d_in[2];
    const void*  graph_id = d_in[3];
    const float* W1 = (const float*)d_in[4];
    const float* b1 = (const float*)d_in[5];
    const float* W2 = (const float*)d_in[6];
    const float* b2 = (const float*)d_in[7];
    const float* W3 = (const float*)d_in[8];
    const float* b3 = (const float*)d_in[9];
    float* out = (float*)d_out;

    float *pA, *pB;
    cudaGetSymbolAddress((void**)&pA, g_bufA);
    cudaGetSymbolAddress((void**)&pB, g_bufB);

    // 0) init + dtype detection
    init_kernel<<<(N_NODES + 255) / 256, 256>>>();
    detect_all_kernel<<<512, 256>>>((const unsigned*)src, (const unsigned*)graph_id);

    // 1) degrees -> norms, CSR build
    deg_kernel<<<2048, 256>>>(src, dst);
    norm_kernel<<<(N_NODES + 255) / 256, 256>>>();
    scan_kernel<<<1, 1024>>>();
    fill_csr_kernel<<<2048, 256>>>(src, dst);

    const int GATHER_GRID = (N_NODES + 7) / 8;     // 8 warps/block

    // 2) layer 1: prescale -> gather(64) -> gemm 64->128 (+relu,*norm_src)
    prescale_kernel<<<(N_NODES * 64 + 255) / 256, 256>>>(h);
    gather_kernel<64><<<GATHER_GRID, 256>>>(pA, pB);
    {
        dim3 blk(128, 2);   // NPB = 16
        gemm_kernel<64, 128, 8, 1><<<N_NODES / 16, blk>>>((const float4*)pB, W1, b1, pA);
    }

    // 3) layer 2: gather(128) -> gemm 128->128 (+relu,*norm_src)
    gather_kernel<128><<<GATHER_GRID, 256>>>(pA, pB);
    {
        dim3 blk(128, 2);   // NPB = 16
        gemm_kernel<128, 128, 8, 1><<<N_NODES / 16, blk>>>((const float4*)pB, W2, b2, pA);
    }

    // 4) layer 3: transform first (gemm 128->64, no epi), then gather+pool
    {
        dim3 blk(64, 4);    // NPB = 32
        gemm_kernel<128, 64, 8, 0><<<N_NODES / 32, blk>>>((const float4*)pA, W3, nullptr, pB);
    }
    zero_out_kernel<<<(N_GRAPHS * 64 + 255) / 256, 256>>>(out, N_GRAPHS * 64);
    gather_pool_kernel<<<GATHER_GRID, 256>>>(pB, b3, graph_id, out);
}